// round 16
// baseline (speedup 1.0000x reference)
#include <cuda_runtime.h>
#include <cuda_fp16.h>
#include <cstdint>

// Problem constants (fixed by the reference)
constexpr long long Nn = 50000;
constexpr long long Ee = 800000;
constexpr long long RP = 50008;   // rowptr stride (>= Nn+1, multiple of 4)

// Scratch layout inside one __device__ array (units of float = 4B).
constexpr long long OFF_DINV1 = 0;
constexpr long long OFF_DINV2 = OFF_DINV1 + Nn;
constexpr long long OFF_CNT1  = OFF_DINV2 + Nn;            // int
constexpr long long OFF_CNT2  = OFF_CNT1  + Nn;            // int
constexpr long long OFF_RP1   = OFF_CNT2  + Nn;            // int rowptr
constexpr long long OFF_RP2   = OFF_RP1   + RP;
constexpr long long OFF_FP1   = OFF_RP2   + RP;            // int fill cursor
constexpr long long OFF_FP2   = OFF_FP1   + Nn;
constexpr long long OFF_BS1   = OFF_FP2   + Nn;            // int block sums [64]
constexpr long long OFF_BS2   = OFF_BS1   + 64;
constexpr long long OFF_IDX1  = OFF_BS2   + 64;            // src1,dst1 [2E] int
constexpr long long OFF_IDX2  = OFF_IDX1  + 2 * Ee;        // src2,dst2 [2E] int
constexpr long long OFF_ADJ1  = OFF_IDX2  + 2 * Ee;        // CSR adj   [E] int
constexpr long long OFF_ADJ2  = OFF_ADJ1  + Ee;
constexpr long long OFF_XS1   = OFF_ADJ2  + Ee;            // x*dinv1 half [N,128]
constexpr long long OFF_XS2   = OFF_XS1   + Nn * 64;
constexpr long long OFF_XA1   = OFF_XS2   + Nn * 64;       // agg(x) half  [N,128]
constexpr long long OFF_XA2   = OFF_XA1   + Nn * 64;
constexpr long long OFF_H1    = OFF_XA2   + Nn * 64;       // relu half    [N,256]
constexpr long long OFF_H2    = OFF_H1    + Nn * 128;
constexpr long long OFF_GS1   = OFF_H2    + Nn * 128;      // g*dinv half  [N,128]
constexpr long long OFF_GS2   = OFF_GS1   + Nn * 64;
constexpr long long OFF_T1    = OFF_GS2   + Nn * 64;       // graph1 term fp32 [N,128]
constexpr long long OFF_WH0   = OFF_T1    + Nn * 128;      // W0^T half [256][128]
constexpr long long OFF_WH1   = OFF_WH0   + 16384;
constexpr long long OFF_WH2   = OFF_WH1   + 16384;         // W2^T half [128][256]
constexpr long long OFF_WH3   = OFF_WH2   + 16384;
constexpr long long SCRATCH   = OFF_WH3   + 16384;

__device__ float g_scratch[SCRATCH];
// 1 if edge indices are int64, 0 if int32. Statically 1; k_detect_zero clears
// it iff the data is int32. Deterministic for fixed input.
__device__ int g_is64 = 1;

// ---------------------------------------------------------------------------
// detect (sampled) + zero BOTH graphs' degree counters (cnt1,cnt2 contiguous)
// ---------------------------------------------------------------------------
__global__ void k_detect_zero(const long long* __restrict__ p, int words, int n,
                              int* __restrict__ cnt, int nzero) {
    int i = blockIdx.x * blockDim.x + threadIdx.x;
    if (i < nzero) cnt[i] = 0;
    if (i < words) {
        long long v = p[i];
        if (v < 0 || v >= n) g_is64 = 0;   // benign race: all writers write 0
    }
}

// decode ONE graph's indices + degree histogram of the dst half
__global__ void k_convert_deg1(const void* __restrict__ p, int* __restrict__ o,
                               int E2, int E, int* __restrict__ cnt) {
    int i = blockIdx.x * blockDim.x + threadIdx.x;
    if (i < E2) {
        int v = g_is64 ? (int)((const long long*)p)[i] : ((const int*)p)[i];
        o[i] = v;
        if (i >= E) atomicAdd(&cnt[v], 1);
    }
}

// ---------------------------------------------------------------------------
// multi-block exclusive scan (2 phases) + dinv compute
// ---------------------------------------------------------------------------
__global__ __launch_bounds__(1024) void k_scan_a(const int* __restrict__ cnt,
                                                 int* __restrict__ rp,
                                                 float* __restrict__ dinv,
                                                 int* __restrict__ bsum, int n) {
    __shared__ int wsum[32];
    const int t = threadIdx.x;
    const int lane = t & 31, wid = t >> 5;
    int i = blockIdx.x * 1024 + t;
    int v = (i < n) ? cnt[i] : 0;
    if (i < n) dinv[i] = rsqrtf((float)v + 1.0f);
    int incl = v;
#pragma unroll
    for (int off = 1; off < 32; off <<= 1) {
        int x = __shfl_up_sync(0xffffffffu, incl, off);
        if (lane >= off) incl += x;
    }
    if (lane == 31) wsum[wid] = incl;
    __syncthreads();
    if (wid == 0) {
        int s = wsum[lane];
#pragma unroll
        for (int off = 1; off < 32; off <<= 1) {
            int x = __shfl_up_sync(0xffffffffu, s, off);
            if (lane >= off) s += x;
        }
        wsum[lane] = s;
    }
    __syncthreads();
    int warpoff = (wid == 0) ? 0 : wsum[wid - 1];
    if (i < n) rp[i] = warpoff + incl - v;
    if (t == 0) bsum[blockIdx.x] = wsum[31];
}

// phase C: each block computes its own bsum prefix from smem (nb <= 64) and
// adds it; mirrors into fill cursor. (No separate scan_b kernel needed.)
__global__ __launch_bounds__(1024) void k_scan_c(int* __restrict__ rp, int* __restrict__ fp,
                                                 const int* __restrict__ bsum, int nb, int n) {
    __shared__ int s[64];
    int t = threadIdx.x;
    if (t < 64) s[t] = (t < nb) ? bsum[t] : 0;
    __syncthreads();
    int off = 0;
    for (int b = 0; b < blockIdx.x; b++) off += s[b];   // smem broadcast reads
    int i = blockIdx.x * 1024 + t;
    if (i < n) {
        int v = rp[i] + off;
        rp[i] = v;
        fp[i] = v;
    }
}

__global__ void k_fill1(const int* __restrict__ src, const int* __restrict__ dst,
                        int* __restrict__ fp, int* __restrict__ adj, int E) {
    int e = blockIdx.x * blockDim.x + threadIdx.x;
    if (e < E) {
        int p = atomicAdd(&fp[dst[e]], 1);
        adj[p] = src[e];
    }
}

// prescale to half: Xs[i] = x[i] * dinv[row], packed half2x2 per float4
__global__ void k_prescale_h(const float4* __restrict__ x, const float* __restrict__ dinv,
                             uint2* __restrict__ Xs, int total4) {
    int i = blockIdx.x * blockDim.x + threadIdx.x;
    if (i < total4) {
        int row = i >> 5;
        float4 v = x[i];
        float d = dinv[row];
        uint2 o;
        *(__half2*)&o.x = __floats2half2_rn(v.x * d, v.y * d);
        *(__half2*)&o.y = __floats2half2_rn(v.z * d, v.w * d);
        Xs[i] = o;
    }
}

// weight prep: Wh[n*K + k] = half(W[k*N + n])  (transpose + halve, all 4)
__global__ void k_prep_w(const float* __restrict__ W0, const float* __restrict__ W1,
                         const float* __restrict__ W2, const float* __restrict__ W3,
                         __half* __restrict__ Wh0, __half* __restrict__ Wh1,
                         __half* __restrict__ Wh2, __half* __restrict__ Wh3) {
    int id = blockIdx.x * 256 + threadIdx.x;       // 0..131071
    int seg = id >> 15;
    int local = id & 32767;
    const float* W;
    __half* Wh;
    int K, Nc;
    if (seg == 0)      { W = W0; Wh = Wh0; K = 128; Nc = 256; }
    else if (seg == 1) { W = W1; Wh = Wh1; K = 128; Nc = 256; }
    else if (seg == 2) { W = W2; Wh = Wh2; K = 256; Nc = 128; }
    else               { W = W3; Wh = Wh3; K = 256; Nc = 128; }
    int k = local / Nc, n = local % Nc;            // coalesced read
    Wh[n * K + k] = __float2half_rn(W[local]);
}

// ---------------------------------------------------------------------------
// gathers (half2 payload, fp32 accumulate). One warp per node, 4 cols/thread.
// Row length comes from cnt[] so rp[N] is never needed.
// ---------------------------------------------------------------------------
// Xa[node] = half( x[node]*dinv^2 + dinv * sum Xs[adj] )
__global__ __launch_bounds__(256) void k_gather_xa(const int* __restrict__ rowptr,
                                                   const int* __restrict__ cnt,
                                                   const int* __restrict__ adj,
                                                   const float* __restrict__ dinv,
                                                   const uint2* __restrict__ Xs,
                                                   const float4* __restrict__ xself,
                                                   uint2* __restrict__ Xa, int N) {
    int node = blockIdx.x * 8 + (threadIdx.x >> 5);
    int c = threadIdx.x & 31;
    if (node >= N) return;
    int beg = rowptr[node];
    int end = beg + cnt[node];
    float s0 = 0.f, s1 = 0.f, s2 = 0.f, s3 = 0.f;
    int j = beg;
    for (; j + 2 <= end; j += 2) {
        uint2 h0 = Xs[(long long)adj[j] * 32 + c];
        uint2 h1 = Xs[(long long)adj[j + 1] * 32 + c];
        float2 a0 = __half22float2(*(__half2*)&h0.x), a1 = __half22float2(*(__half2*)&h0.y);
        float2 b0 = __half22float2(*(__half2*)&h1.x), b1 = __half22float2(*(__half2*)&h1.y);
        s0 += a0.x + b0.x; s1 += a0.y + b0.y;
        s2 += a1.x + b1.x; s3 += a1.y + b1.y;
    }
    if (j < end) {
        uint2 h0 = Xs[(long long)adj[j] * 32 + c];
        float2 a0 = __half22float2(*(__half2*)&h0.x), a1 = __half22float2(*(__half2*)&h0.y);
        s0 += a0.x; s1 += a0.y; s2 += a1.x; s3 += a1.y;
    }
    float w = dinv[node], w2 = w * w;
    float4 sv = xself[(long long)node * 32 + c];
    uint2 o;
    *(__half2*)&o.x = __floats2half2_rn(sv.x * w2 + s0 * w, sv.y * w2 + s1 * w);
    *(__half2*)&o.y = __floats2half2_rn(sv.z * w2 + s2 * w, sv.w * w2 + s3 * w);
    Xa[(long long)node * 32 + c] = o;
}

// GM=2: Out[node]  = dinv * sum Gs[adj]               (fp32 T1)
// GM=3: Out[node] += T[node] + dinv * sum Gs[adj]     (fp32 out, final join)
template <int GM>
__global__ __launch_bounds__(256) void k_gather_out(const int* __restrict__ rowptr,
                                                    const int* __restrict__ cnt,
                                                    const int* __restrict__ adj,
                                                    const float* __restrict__ dinv,
                                                    const uint2* __restrict__ Gs,
                                                    const float4* __restrict__ T,
                                                    float4* __restrict__ Out, int N) {
    int node = blockIdx.x * 8 + (threadIdx.x >> 5);
    int c = threadIdx.x & 31;
    if (node >= N) return;
    int beg = rowptr[node];
    int end = beg + cnt[node];
    float s0 = 0.f, s1 = 0.f, s2 = 0.f, s3 = 0.f;
    int j = beg;
    for (; j + 2 <= end; j += 2) {
        uint2 h0 = Gs[(long long)adj[j] * 32 + c];
        uint2 h1 = Gs[(long long)adj[j + 1] * 32 + c];
        float2 a0 = __half22float2(*(__half2*)&h0.x), a1 = __half22float2(*(__half2*)&h0.y);
        float2 b0 = __half22float2(*(__half2*)&h1.x), b1 = __half22float2(*(__half2*)&h1.y);
        s0 += a0.x + b0.x; s1 += a0.y + b0.y;
        s2 += a1.x + b1.x; s3 += a1.y + b1.y;
    }
    if (j < end) {
        uint2 h0 = Gs[(long long)adj[j] * 32 + c];
        float2 a0 = __half22float2(*(__half2*)&h0.x), a1 = __half22float2(*(__half2*)&h0.y);
        s0 += a0.x; s1 += a0.y; s2 += a1.x; s3 += a1.y;
    }
    float w = dinv[node];
    long long p = (long long)node * 32 + c;
    float4 a;
    if (GM == 2) {
        a = make_float4(0.f, 0.f, 0.f, 0.f);
    } else {
        float4 o = Out[p];
        float4 tv = T[p];
        a = make_float4(o.x + tv.x, o.y + tv.y, o.z + tv.z, o.w + tv.w);
    }
    a.x += s0 * w; a.y += s1 * w; a.z += s2 * w; a.w += s3 * w;
    Out[p] = a;
}

// ---------------------------------------------------------------------------
// fp16 tensor-core GEMM (m16n8k16, fp32 accum), cp.async double buffering,
// ldmatrix fragment loads.
//   C = A[M,KT] * Wh^T  where Wh is [Ncol][KT] half (pre-transposed weights).
//   BM=128, BN=64, BK=32; 256 threads = 8 warps (4 M x 2 N), warp tile 32x32.
// MODE 0: OutH = half(relu(acc + bias2[c]))                       (layer 1)
// MODE 1: OutS = half(acc*dv) ; OutF  = acc*dv^2 + bias2 + bias3  (layer 2a)
// MODE 2: OutS = half(acc*dv) ; OutF += acc*dv^2                  (layer 2b)
// ---------------------------------------------------------------------------
__device__ __forceinline__ void mma_f16(float* c, uint32_t a0, uint32_t a1,
                                        uint32_t a2, uint32_t a3,
                                        uint32_t b0, uint32_t b1) {
    asm volatile(
        "mma.sync.aligned.m16n8k16.row.col.f32.f16.f16.f32 "
        "{%0,%1,%2,%3}, {%4,%5,%6,%7}, {%8,%9}, {%0,%1,%2,%3};\n"
        : "+f"(c[0]), "+f"(c[1]), "+f"(c[2]), "+f"(c[3])
        : "r"(a0), "r"(a1), "r"(a2), "r"(a3), "r"(b0), "r"(b1));
}

__device__ __forceinline__ uint32_t smem_u32(const void* p) {
    return (uint32_t)__cvta_generic_to_shared(p);
}
__device__ __forceinline__ void ldsm_x4(uint32_t& r0, uint32_t& r1,
                                        uint32_t& r2, uint32_t& r3, uint32_t addr) {
    asm volatile("ldmatrix.sync.aligned.m8n8.x4.shared.b16 {%0,%1,%2,%3}, [%4];"
                 : "=r"(r0), "=r"(r1), "=r"(r2), "=r"(r3) : "r"(addr));
}
__device__ __forceinline__ void cp16(uint32_t dst, const void* src, int sz) {
    asm volatile("cp.async.cg.shared.global [%0], [%1], 16, %2;\n"
                 :: "r"(dst), "l"(src), "r"(sz));
}
__device__ __forceinline__ void cp_commit() {
    asm volatile("cp.async.commit_group;\n");
}
template <int N_> __device__ __forceinline__ void cp_wait() {
    asm volatile("cp.async.wait_group %0;\n" :: "n"(N_));
}

template <int MODE, int KT>
__global__ __launch_bounds__(256) void k_gemm_h(const __half* __restrict__ A,
                                                const __half* __restrict__ B,   // Wh [Ncol][KT]
                                                const float* __restrict__ dinv,
                                                __half* __restrict__ OutS,      // Gs half
                                                __half* __restrict__ OutH,      // H half
                                                float* __restrict__ OutF,       // out fp32
                                                const float* __restrict__ bias2,
                                                const float* __restrict__ bias3,
                                                int M, int Ncol) {
    __shared__ __half As[2][128 * 40];   // pad 40 halves/row
    __shared__ __half Bs[2][64 * 40];

    const int tid  = threadIdx.x;
    const int wid  = tid >> 5;
    const int lane = tid & 31;
    const int gid  = lane >> 2;     // 0..7
    const int tig  = lane & 3;      // 0..3
    const int wm   = wid >> 1;      // 0..3
    const int wn   = wid & 1;       // 0..1
    const int rowBase = blockIdx.y * 128;
    const int colBase = blockIdx.x * 64;
    constexpr int NK = KT / 32;

    auto loadTiles = [&](int i) {
        int k0 = i * 32;
        int buf = i & 1;
        // A: 128 rows x 32 half = 512 x 16B chunks, 2 per thread
#pragma unroll
        for (int t = 0; t < 2; t++) {
            int idx = tid + t * 256;        // 0..511
            int r   = idx >> 2;
            int ch  = idx & 3;
            int row = rowBase + r;
            const __half* g = A + (long long)(row < M ? row : 0) * KT + k0 + ch * 8;
            cp16(smem_u32(&As[buf][r * 40 + ch * 8]), g, row < M ? 16 : 0);
        }
        // B: 64 n-rows x 32 half = 256 chunks, 1 per thread
        {
            int n  = tid >> 2;
            int ch = tid & 3;
            const __half* g = B + (long long)(colBase + n) * KT + k0 + ch * 8;
            cp16(smem_u32(&Bs[buf][n * 40 + ch * 8]), g, 16);
        }
        cp_commit();
    };

    float acc[2][4][4] = {};
    loadTiles(0);

    // ldmatrix lane-address components (constant across iterations)
    const int aRow = (lane & 15);            // row within warp M-tile
    const int aKof = (lane >> 4) << 3;       // 0 or 8 (k-half)
    const int bRow = wn * 32 + lane;         // n row for B x4 (4 nt matrices)

#pragma unroll
    for (int i = 0; i < NK; i++) {
        if (i + 1 < NK) loadTiles(i + 1);
        if (i + 1 < NK) cp_wait<1>(); else cp_wait<0>();
        __syncthreads();

        const __half* as = As[i & 1];
        const __half* bs = Bs[i & 1];
#pragma unroll
        for (int ks = 0; ks < 32; ks += 16) {
            uint32_t a[2][4];
#pragma unroll
            for (int mt = 0; mt < 2; mt++) {
                uint32_t addr = smem_u32(as + (wm * 32 + mt * 16 + aRow) * 40 + ks + aKof);
                ldsm_x4(a[mt][0], a[mt][1], a[mt][2], a[mt][3], addr);
            }
            uint32_t b[2][4];   // [k-half][nt]
#pragma unroll
            for (int h = 0; h < 2; h++) {
                uint32_t addr = smem_u32(bs + bRow * 40 + ks + h * 8);
                ldsm_x4(b[h][0], b[h][1], b[h][2], b[h][3], addr);
            }
#pragma unroll
            for (int mt = 0; mt < 2; mt++)
#pragma unroll
                for (int nt = 0; nt < 4; nt++)
                    mma_f16(acc[mt][nt], a[mt][0], a[mt][1], a[mt][2], a[mt][3],
                            b[0][nt], b[1][nt]);
        }
        __syncthreads();
    }

    // epilogue: c0,c1 -> row gid (cols 2tig,2tig+1); c2,c3 -> row gid+8
#pragma unroll
    for (int mt = 0; mt < 2; mt++) {
#pragma unroll
        for (int h = 0; h < 2; h++) {
            int row = rowBase + wm * 32 + mt * 16 + gid + h * 8;
            if (row >= M) continue;
            float dv  = (MODE == 0) ? 0.f : dinv[row];
            float dv2 = dv * dv;
            long long rb = (long long)row * Ncol;
#pragma unroll
            for (int nt = 0; nt < 4; nt++) {
                int c = colBase + wn * 32 + nt * 8 + 2 * tig;
                float v0 = acc[mt][nt][2 * h + 0];
                float v1 = acc[mt][nt][2 * h + 1];
                if (MODE == 0) {
                    float2 bb = *(const float2*)(bias2 + c);
                    *(__half2*)(OutH + rb + c) =
                        __floats2half2_rn(fmaxf(v0 + bb.x, 0.f), fmaxf(v1 + bb.y, 0.f));
                } else if (MODE == 1) {
                    *(__half2*)(OutS + rb + c) = __floats2half2_rn(v0 * dv, v1 * dv);
                    float2 p2 = *(const float2*)(bias2 + c);
                    float2 p3 = *(const float2*)(bias3 + c);
                    *(float2*)(OutF + rb + c) =
                        make_float2(v0 * dv2 + p2.x + p3.x, v1 * dv2 + p2.y + p3.y);
                } else {
                    *(__half2*)(OutS + rb + c) = __floats2half2_rn(v0 * dv, v1 * dv);
                    float2 o = *(const float2*)(OutF + rb + c);
                    o.x += v0 * dv2;
                    o.y += v1 * dv2;
                    *(float2*)(OutF + rb + c) = o;
                }
            }
        }
    }
}

// ---------------------------------------------------------------------------
// host side: two-stream schedule, all record-before-wait in program order
// (required under stream capture). Tensor-bound GEMMs serialized on s0;
// L2-bound graph-2 / T1 gathers run under them on s2.
// ---------------------------------------------------------------------------
static cudaStream_t g_s2    = nullptr;
static cudaEvent_t  g_evF   = nullptr;   // fork point (s0, first)
static cudaEvent_t  g_evW   = nullptr;   // weights prepped (s2)
static cudaEvent_t  g_evX1  = nullptr;   // after gather Xa1 (stagger gate, s0)
static cudaEvent_t  g_evXa2 = nullptr;   // after gather Xa2 (s2)
static cudaEvent_t  g_evM1  = nullptr;   // after GEMM MODE1 (s0)
static cudaEvent_t  g_evT1  = nullptr;   // after gather T1 (s2, join point)

extern "C" void kernel_launch(void* const* d_in, const int* in_sizes, int n_in,
                              void* d_out, int out_size) {
    if (!g_s2) {
        cudaStreamCreateWithFlags(&g_s2, cudaStreamNonBlocking);
        cudaEventCreateWithFlags(&g_evF,   cudaEventDisableTiming);
        cudaEventCreateWithFlags(&g_evW,   cudaEventDisableTiming);
        cudaEventCreateWithFlags(&g_evX1,  cudaEventDisableTiming);
        cudaEventCreateWithFlags(&g_evXa2, cudaEventDisableTiming);
        cudaEventCreateWithFlags(&g_evM1,  cudaEventDisableTiming);
        cudaEventCreateWithFlags(&g_evT1,  cudaEventDisableTiming);
    }

    const float* x   = (const float*)d_in[0];
    const void*  ei  = d_in[1];
    const void*  ei2 = d_in[2];
    const float* W0 = (const float*)d_in[3];
    const float* b0 = (const float*)d_in[4];
    const float* W1 = (const float*)d_in[5];
    const float* b1 = (const float*)d_in[6];
    const float* W2 = (const float*)d_in[7];
    const float* b2 = (const float*)d_in[8];
    const float* W3 = (const float*)d_in[9];
    const float* b3 = (const float*)d_in[10];

    const int N = in_sizes[0] / 128;   // 50000
    const int E = in_sizes[1] / 2;     // 800000
    const int NB = (N + 1023) / 1024;  // scan blocks (49)

    float* S = nullptr;
    cudaGetSymbolAddress((void**)&S, g_scratch);
    float*  dinv1 = S + OFF_DINV1;
    float*  dinv2 = S + OFF_DINV2;
    int*    cnt1  = (int*)(S + OFF_CNT1);
    int*    cnt2  = (int*)(S + OFF_CNT2);
    int*    rp1   = (int*)(S + OFF_RP1);
    int*    rp2   = (int*)(S + OFF_RP2);
    int*    fp1   = (int*)(S + OFF_FP1);
    int*    fp2   = (int*)(S + OFF_FP2);
    int*    bs1   = (int*)(S + OFF_BS1);
    int*    bs2   = (int*)(S + OFF_BS2);
    int*    idx1  = (int*)(S + OFF_IDX1);
    int*    idx2  = (int*)(S + OFF_IDX2);
    int*    adj1  = (int*)(S + OFF_ADJ1);
    int*    adj2  = (int*)(S + OFF_ADJ2);
    __half* Xs1   = (__half*)(S + OFF_XS1);
    __half* Xs2   = (__half*)(S + OFF_XS2);
    __half* Xa1   = (__half*)(S + OFF_XA1);
    __half* Xa2   = (__half*)(S + OFF_XA2);
    __half* H1    = (__half*)(S + OFF_H1);
    __half* H2    = (__half*)(S + OFF_H2);
    __half* Gs1   = (__half*)(S + OFF_GS1);
    __half* Gs2   = (__half*)(S + OFF_GS2);
    float*  T1    = S + OFF_T1;
    __half* Wh0   = (__half*)(S + OFF_WH0);
    __half* Wh1   = (__half*)(S + OFF_WH1);
    __half* Wh2   = (__half*)(S + OFF_WH2);
    __half* Wh3   = (__half*)(S + OFF_WH3);
    float*  out   = (float*)d_out;

    cudaStream_t s0 = 0;
    cudaStream_t s2 = g_s2;

    const int* src1 = idx1;
    const int* dst1 = idx1 + E;
    const int* src2 = idx2;
    const int* dst2 = idx2 + E;

    // ---- (1) s0: first kernel (dtype probe + zero BOTH counters), record evF
    {
        int words = (E < 65536) ? E : 65536;
        int span  = (2 * N > words) ? 2 * N : words;
        k_detect_zero<<<(span + 255) / 256, 256, 0, s0>>>((const long long*)ei, words, N, cnt1, 2 * N);
    }
    cudaEventRecord(g_evF, s0);

    // ---- (2) s2 joins capture: weight prep + graph-2 prelim (no forward waits)
    cudaStreamWaitEvent(s2, g_evF, 0);
    k_prep_w<<<512, 256, 0, s2>>>(W0, W1, W2, W3, Wh0, Wh1, Wh2, Wh3);
    cudaEventRecord(g_evW, s2);
    k_convert_deg1<<<(2 * E + 255) / 256, 256, 0, s2>>>(ei2, idx2, 2 * E, E, cnt2);
    k_scan_a<<<NB, 1024, 0, s2>>>(cnt2, rp2, dinv2, bs2, N);
    k_scan_c<<<NB, 1024, 0, s2>>>(rp2, fp2, bs2, NB, N);
    k_fill1<<<(E + 255) / 256, 256, 0, s2>>>(src2, dst2, fp2, adj2, E);
    k_prescale_h<<<(N * 32 + 255) / 256, 256, 0, s2>>>((const float4*)x, dinv2, (uint2*)Xs2, N * 32);

    // ---- (3) s0: graph-1 chain, record evX1
    k_convert_deg1<<<(2 * E + 255) / 256, 256, 0, s0>>>(ei, idx1, 2 * E, E, cnt1);
    k_scan_a<<<NB, 1024, 0, s0>>>(cnt1, rp1, dinv1, bs1, N);
    k_scan_c<<<NB, 1024, 0, s0>>>(rp1, fp1, bs1, NB, N);
    k_fill1<<<(E + 255) / 256, 256, 0, s0>>>(src1, dst1, fp1, adj1, E);
    k_prescale_h<<<(N * 32 + 255) / 256, 256, 0, s0>>>((const float4*)x, dinv1, (uint2*)Xs1, N * 32);
    k_gather_xa<<<(N + 7) / 8, 256, 0, s0>>>(rp1, cnt1, adj1, dinv1, (const uint2*)Xs1,
                                             (const float4*)x, (uint2*)Xa1, N);
    cudaEventRecord(g_evX1, s0);

    // ---- (4) s2: gather Xa2 staggered under H1 (evX1 already recorded)
    cudaStreamWaitEvent(s2, g_evX1, 0);
    k_gather_xa<<<(N + 7) / 8, 256, 0, s2>>>(rp2, cnt2, adj2, dinv2, (const uint2*)Xs2,
                                             (const float4*)x, (uint2*)Xa2, N);
    cudaEventRecord(g_evXa2, s2);

    // ---- (5) s0: GEMMs H1, MODE1 (serial on tensor pipe), record evM1
    dim3 g1(4, (N + 127) / 128);   // layer-1: KT=128, Ncol=256
    dim3 g2(2, (N + 127) / 128);   // layer-2: KT=256, Ncol=128
    cudaStreamWaitEvent(s0, g_evW, 0);
    k_gemm_h<0, 128><<<g1, 256, 0, s0>>>(Xa1, Wh0, nullptr, nullptr, H1, nullptr, b0, nullptr, N, 256);
    k_gemm_h<1, 256><<<g2, 256, 0, s0>>>(H1, Wh2, dinv1, Gs1, nullptr, out, b2, b3, N, 128);
    cudaEventRecord(g_evM1, s0);

    // ---- (6) s2: graph-1 output gather into T1, hidden under H2+MODE2
    cudaStreamWaitEvent(s2, g_evM1, 0);
    k_gather_out<2><<<(N + 7) / 8, 256, 0, s2>>>(rp1, cnt1, adj1, dinv1, (const uint2*)Gs1,
                                                 nullptr, (float4*)T1, N);
    cudaEventRecord(g_evT1, s2);

    // ---- (7) s0: GEMMs H2, MODE2 (evXa2 already recorded)
    cudaStreamWaitEvent(s0, g_evXa2, 0);
    k_gemm_h<0, 128><<<g1, 256, 0, s0>>>(Xa2, Wh1, nullptr, nullptr, H2, nullptr, b1, nullptr, N, 256);
    k_gemm_h<2, 256><<<g2, 256, 0, s0>>>(H2, Wh3, dinv2, Gs2, nullptr, out, nullptr, nullptr, N, 128);

    // ---- (8) s0: final graph-2 gather + T1 add fused into out (join on evT1)
    cudaStreamWaitEvent(s0, g_evT1, 0);
    k_gather_out<3><<<(N + 7) / 8, 256, 0, s0>>>(rp2, cnt2, adj2, dinv2, (const uint2*)Gs2,
                                                 (const float4*)T1, (float4*)out, N);
}

// round 17
// speedup vs baseline: 1.0339x; 1.0339x over previous
#include <cuda_runtime.h>
#include <cuda_fp16.h>
#include <cstdint>

// Problem constants (fixed by the reference)
constexpr long long Nn = 50000;
constexpr long long Ee = 800000;
constexpr long long RP = 50008;   // rowptr stride (>= Nn+1, multiple of 4)

// Scratch layout inside one __device__ array (units of float = 4B).
constexpr long long OFF_DINV1 = 0;
constexpr long long OFF_DINV2 = OFF_DINV1 + Nn;
constexpr long long OFF_CNT1  = OFF_DINV2 + Nn;            // int
constexpr long long OFF_CNT2  = OFF_CNT1  + Nn;            // int
constexpr long long OFF_RP1   = OFF_CNT2  + Nn;            // int rowptr
constexpr long long OFF_RP2   = OFF_RP1   + RP;
constexpr long long OFF_FP1   = OFF_RP2   + RP;            // int fill cursor
constexpr long long OFF_FP2   = OFF_FP1   + Nn;
constexpr long long OFF_BS1   = OFF_FP2   + Nn;            // int block sums [64]
constexpr long long OFF_BS2   = OFF_BS1   + 64;
constexpr long long OFF_IDX1  = OFF_BS2   + 64;            // src1,dst1 [2E] int
constexpr long long OFF_IDX2  = OFF_IDX1  + 2 * Ee;        // src2,dst2 [2E] int
constexpr long long OFF_ADJ1  = OFF_IDX2  + 2 * Ee;        // CSR adj   [E] int
constexpr long long OFF_ADJ2  = OFF_ADJ1  + Ee;
constexpr long long OFF_XS1   = OFF_ADJ2  + Ee;            // x*dinv1 half [N,128]
constexpr long long OFF_XS2   = OFF_XS1   + Nn * 64;
constexpr long long OFF_XA1   = OFF_XS2   + Nn * 64;       // agg(x) half  [N,128]
constexpr long long OFF_XA2   = OFF_XA1   + Nn * 64;
constexpr long long OFF_H1    = OFF_XA2   + Nn * 64;       // relu half    [N,256]
constexpr long long OFF_H2    = OFF_H1    + Nn * 128;
constexpr long long OFF_GS1   = OFF_H2    + Nn * 128;      // g*dinv half  [N,128]
constexpr long long OFF_GS2   = OFF_GS1   + Nn * 64;
constexpr long long OFF_T1    = OFF_GS2   + Nn * 64;       // graph1 term fp32 [N,128]
constexpr long long OFF_WH0   = OFF_T1    + Nn * 128;      // W0^T half [256][128]
constexpr long long OFF_WH1   = OFF_WH0   + 16384;
constexpr long long OFF_WH2   = OFF_WH1   + 16384;         // W2^T half [128][256]
constexpr long long OFF_WH3   = OFF_WH2   + 16384;
constexpr long long SCRATCH   = OFF_WH3   + 16384;

__device__ float g_scratch[SCRATCH];
// 1 if edge indices are int64, 0 if int32. Statically 1; k_detect_zero clears
// it iff the data is int32. Deterministic for fixed input.
__device__ int g_is64 = 1;

// ---------------------------------------------------------------------------
// detect (sampled) + zero BOTH graphs' degree counters (cnt1,cnt2 contiguous)
// ---------------------------------------------------------------------------
__global__ void k_detect_zero(const long long* __restrict__ p, int words, int n,
                              int* __restrict__ cnt, int nzero) {
    int i = blockIdx.x * blockDim.x + threadIdx.x;
    if (i < nzero) cnt[i] = 0;
    if (i < words) {
        long long v = p[i];
        if (v < 0 || v >= n) g_is64 = 0;   // benign race: all writers write 0
    }
}

// decode ONE graph's indices + degree histogram of the dst half
__global__ void k_convert_deg1(const void* __restrict__ p, int* __restrict__ o,
                               int E2, int E, int* __restrict__ cnt) {
    int i = blockIdx.x * blockDim.x + threadIdx.x;
    if (i < E2) {
        int v = g_is64 ? (int)((const long long*)p)[i] : ((const int*)p)[i];
        o[i] = v;
        if (i >= E) atomicAdd(&cnt[v], 1);
    }
}

// ---------------------------------------------------------------------------
// multi-block exclusive scan (2 phases) + dinv compute
// ---------------------------------------------------------------------------
__global__ __launch_bounds__(1024) void k_scan_a(const int* __restrict__ cnt,
                                                 int* __restrict__ rp,
                                                 float* __restrict__ dinv,
                                                 int* __restrict__ bsum, int n) {
    __shared__ int wsum[32];
    const int t = threadIdx.x;
    const int lane = t & 31, wid = t >> 5;
    int i = blockIdx.x * 1024 + t;
    int v = (i < n) ? cnt[i] : 0;
    if (i < n) dinv[i] = rsqrtf((float)v + 1.0f);
    int incl = v;
#pragma unroll
    for (int off = 1; off < 32; off <<= 1) {
        int x = __shfl_up_sync(0xffffffffu, incl, off);
        if (lane >= off) incl += x;
    }
    if (lane == 31) wsum[wid] = incl;
    __syncthreads();
    if (wid == 0) {
        int s = wsum[lane];
#pragma unroll
        for (int off = 1; off < 32; off <<= 1) {
            int x = __shfl_up_sync(0xffffffffu, s, off);
            if (lane >= off) s += x;
        }
        wsum[lane] = s;
    }
    __syncthreads();
    int warpoff = (wid == 0) ? 0 : wsum[wid - 1];
    if (i < n) rp[i] = warpoff + incl - v;
    if (t == 0) bsum[blockIdx.x] = wsum[31];
}

// phase C: each block computes its own bsum prefix from smem (nb <= 64) and
// adds it; mirrors into fill cursor.
__global__ __launch_bounds__(1024) void k_scan_c(int* __restrict__ rp, int* __restrict__ fp,
                                                 const int* __restrict__ bsum, int nb, int n) {
    __shared__ int s[64];
    int t = threadIdx.x;
    if (t < 64) s[t] = (t < nb) ? bsum[t] : 0;
    __syncthreads();
    int off = 0;
    for (int b = 0; b < blockIdx.x; b++) off += s[b];   // smem broadcast reads
    int i = blockIdx.x * 1024 + t;
    if (i < n) {
        int v = rp[i] + off;
        rp[i] = v;
        fp[i] = v;
    }
}

__global__ void k_fill1(const int* __restrict__ src, const int* __restrict__ dst,
                        int* __restrict__ fp, int* __restrict__ adj, int E) {
    int e = blockIdx.x * blockDim.x + threadIdx.x;
    if (e < E) {
        int p = atomicAdd(&fp[dst[e]], 1);
        adj[p] = src[e];
    }
}

// prescale to half: Xs[i] = x[i] * dinv[row], packed half2x2 per float4
__global__ void k_prescale_h(const float4* __restrict__ x, const float* __restrict__ dinv,
                             uint2* __restrict__ Xs, int total4) {
    int i = blockIdx.x * blockDim.x + threadIdx.x;
    if (i < total4) {
        int row = i >> 5;
        float4 v = x[i];
        float d = dinv[row];
        uint2 o;
        *(__half2*)&o.x = __floats2half2_rn(v.x * d, v.y * d);
        *(__half2*)&o.y = __floats2half2_rn(v.z * d, v.w * d);
        Xs[i] = o;
    }
}

// weight prep: Wh[n*K + k] = half(W[k*N + n])  (transpose + halve, all 4)
__global__ void k_prep_w(const float* __restrict__ W0, const float* __restrict__ W1,
                         const float* __restrict__ W2, const float* __restrict__ W3,
                         __half* __restrict__ Wh0, __half* __restrict__ Wh1,
                         __half* __restrict__ Wh2, __half* __restrict__ Wh3) {
    int id = blockIdx.x * 256 + threadIdx.x;       // 0..131071
    int seg = id >> 15;
    int local = id & 32767;
    const float* W;
    __half* Wh;
    int K, Nc;
    if (seg == 0)      { W = W0; Wh = Wh0; K = 128; Nc = 256; }
    else if (seg == 1) { W = W1; Wh = Wh1; K = 128; Nc = 256; }
    else if (seg == 2) { W = W2; Wh = Wh2; K = 256; Nc = 128; }
    else               { W = W3; Wh = Wh3; K = 256; Nc = 128; }
    int k = local / Nc, n = local % Nc;            // coalesced read
    Wh[n * K + k] = __float2half_rn(W[local]);
}

// ---------------------------------------------------------------------------
// gathers (half2 payload, fp32 accumulate). One warp per node, 4 cols/thread.
// Row length comes from cnt[] so rp[N] is never needed.
// ---------------------------------------------------------------------------
// Xa[node] = half( x[node]*dinv^2 + dinv * sum Xs[adj] )
__global__ __launch_bounds__(256) void k_gather_xa(const int* __restrict__ rowptr,
                                                   const int* __restrict__ cnt,
                                                   const int* __restrict__ adj,
                                                   const float* __restrict__ dinv,
                                                   const uint2* __restrict__ Xs,
                                                   const float4* __restrict__ xself,
                                                   uint2* __restrict__ Xa, int N) {
    int node = blockIdx.x * 8 + (threadIdx.x >> 5);
    int c = threadIdx.x & 31;
    if (node >= N) return;
    int beg = rowptr[node];
    int end = beg + cnt[node];
    float s0 = 0.f, s1 = 0.f, s2 = 0.f, s3 = 0.f;
    int j = beg;
    for (; j + 2 <= end; j += 2) {
        uint2 h0 = Xs[(long long)adj[j] * 32 + c];
        uint2 h1 = Xs[(long long)adj[j + 1] * 32 + c];
        float2 a0 = __half22float2(*(__half2*)&h0.x), a1 = __half22float2(*(__half2*)&h0.y);
        float2 b0 = __half22float2(*(__half2*)&h1.x), b1 = __half22float2(*(__half2*)&h1.y);
        s0 += a0.x + b0.x; s1 += a0.y + b0.y;
        s2 += a1.x + b1.x; s3 += a1.y + b1.y;
    }
    if (j < end) {
        uint2 h0 = Xs[(long long)adj[j] * 32 + c];
        float2 a0 = __half22float2(*(__half2*)&h0.x), a1 = __half22float2(*(__half2*)&h0.y);
        s0 += a0.x; s1 += a0.y; s2 += a1.x; s3 += a1.y;
    }
    float w = dinv[node], w2 = w * w;
    float4 sv = xself[(long long)node * 32 + c];
    uint2 o;
    *(__half2*)&o.x = __floats2half2_rn(sv.x * w2 + s0 * w, sv.y * w2 + s1 * w);
    *(__half2*)&o.y = __floats2half2_rn(sv.z * w2 + s2 * w, sv.w * w2 + s3 * w);
    Xa[(long long)node * 32 + c] = o;
}

// GM=2: Out[node]  = dinv * sum Gs[adj]               (fp32 T1)
// GM=3: Out[node] += T[node] + dinv * sum Gs[adj]     (fp32 out, final join)
template <int GM>
__global__ __launch_bounds__(256) void k_gather_out(const int* __restrict__ rowptr,
                                                    const int* __restrict__ cnt,
                                                    const int* __restrict__ adj,
                                                    const float* __restrict__ dinv,
                                                    const uint2* __restrict__ Gs,
                                                    const float4* __restrict__ T,
                                                    float4* __restrict__ Out, int N) {
    int node = blockIdx.x * 8 + (threadIdx.x >> 5);
    int c = threadIdx.x & 31;
    if (node >= N) return;
    int beg = rowptr[node];
    int end = beg + cnt[node];
    float s0 = 0.f, s1 = 0.f, s2 = 0.f, s3 = 0.f;
    int j = beg;
    for (; j + 2 <= end; j += 2) {
        uint2 h0 = Gs[(long long)adj[j] * 32 + c];
        uint2 h1 = Gs[(long long)adj[j + 1] * 32 + c];
        float2 a0 = __half22float2(*(__half2*)&h0.x), a1 = __half22float2(*(__half2*)&h0.y);
        float2 b0 = __half22float2(*(__half2*)&h1.x), b1 = __half22float2(*(__half2*)&h1.y);
        s0 += a0.x + b0.x; s1 += a0.y + b0.y;
        s2 += a1.x + b1.x; s3 += a1.y + b1.y;
    }
    if (j < end) {
        uint2 h0 = Gs[(long long)adj[j] * 32 + c];
        float2 a0 = __half22float2(*(__half2*)&h0.x), a1 = __half22float2(*(__half2*)&h0.y);
        s0 += a0.x; s1 += a0.y; s2 += a1.x; s3 += a1.y;
    }
    float w = dinv[node];
    long long p = (long long)node * 32 + c;
    float4 a;
    if (GM == 2) {
        a = make_float4(0.f, 0.f, 0.f, 0.f);
    } else {
        float4 o = Out[p];
        float4 tv = T[p];
        a = make_float4(o.x + tv.x, o.y + tv.y, o.z + tv.z, o.w + tv.w);
    }
    a.x += s0 * w; a.y += s1 * w; a.z += s2 * w; a.w += s3 * w;
    Out[p] = a;
}

// ---------------------------------------------------------------------------
// fp16 tensor-core GEMM (m16n8k16, fp32 accum), cp.async double buffering,
// ldmatrix fragment loads.
//   C = A[M,KT] * Wh^T  where Wh is [Ncol][KT] half (pre-transposed weights).
//   BM=128, BN=64, BK=32; 256 threads = 8 warps (4 M x 2 N), warp tile 32x32.
// MODE 0: OutH = half(relu(acc + bias2[c]))                       (layer 1)
// MODE 1: OutS = half(acc*dv) ; OutF  = acc*dv^2 + bias2 + bias3  (layer 2a)
// MODE 2: OutS = half(acc*dv) ; OutF += acc*dv^2                  (layer 2b)
// ---------------------------------------------------------------------------
__device__ __forceinline__ void mma_f16(float* c, uint32_t a0, uint32_t a1,
                                        uint32_t a2, uint32_t a3,
                                        uint32_t b0, uint32_t b1) {
    asm volatile(
        "mma.sync.aligned.m16n8k16.row.col.f32.f16.f16.f32 "
        "{%0,%1,%2,%3}, {%4,%5,%6,%7}, {%8,%9}, {%0,%1,%2,%3};\n"
        : "+f"(c[0]), "+f"(c[1]), "+f"(c[2]), "+f"(c[3])
        : "r"(a0), "r"(a1), "r"(a2), "r"(a3), "r"(b0), "r"(b1));
}

__device__ __forceinline__ uint32_t smem_u32(const void* p) {
    return (uint32_t)__cvta_generic_to_shared(p);
}
__device__ __forceinline__ void ldsm_x4(uint32_t& r0, uint32_t& r1,
                                        uint32_t& r2, uint32_t& r3, uint32_t addr) {
    asm volatile("ldmatrix.sync.aligned.m8n8.x4.shared.b16 {%0,%1,%2,%3}, [%4];"
                 : "=r"(r0), "=r"(r1), "=r"(r2), "=r"(r3) : "r"(addr));
}
__device__ __forceinline__ void cp16(uint32_t dst, const void* src, int sz) {
    asm volatile("cp.async.cg.shared.global [%0], [%1], 16, %2;\n"
                 :: "r"(dst), "l"(src), "r"(sz));
}
__device__ __forceinline__ void cp_commit() {
    asm volatile("cp.async.commit_group;\n");
}
template <int N_> __device__ __forceinline__ void cp_wait() {
    asm volatile("cp.async.wait_group %0;\n" :: "n"(N_));
}

template <int MODE, int KT>
__global__ __launch_bounds__(256) void k_gemm_h(const __half* __restrict__ A,
                                                const __half* __restrict__ B,   // Wh [Ncol][KT]
                                                const float* __restrict__ dinv,
                                                __half* __restrict__ OutS,      // Gs half
                                                __half* __restrict__ OutH,      // H half
                                                float* __restrict__ OutF,       // out fp32
                                                const float* __restrict__ bias2,
                                                const float* __restrict__ bias3,
                                                int M, int Ncol) {
    __shared__ __half As[2][128 * 40];   // pad 40 halves/row
    __shared__ __half Bs[2][64 * 40];

    const int tid  = threadIdx.x;
    const int wid  = tid >> 5;
    const int lane = tid & 31;
    const int gid  = lane >> 2;     // 0..7
    const int tig  = lane & 3;      // 0..3
    const int wm   = wid >> 1;      // 0..3
    const int wn   = wid & 1;       // 0..1
    const int rowBase = blockIdx.y * 128;
    const int colBase = blockIdx.x * 64;
    constexpr int NK = KT / 32;

    auto loadTiles = [&](int i) {
        int k0 = i * 32;
        int buf = i & 1;
        // A: 128 rows x 32 half = 512 x 16B chunks, 2 per thread
#pragma unroll
        for (int t = 0; t < 2; t++) {
            int idx = tid + t * 256;        // 0..511
            int r   = idx >> 2;
            int ch  = idx & 3;
            int row = rowBase + r;
            const __half* g = A + (long long)(row < M ? row : 0) * KT + k0 + ch * 8;
            cp16(smem_u32(&As[buf][r * 40 + ch * 8]), g, row < M ? 16 : 0);
        }
        // B: 64 n-rows x 32 half = 256 chunks, 1 per thread
        {
            int n  = tid >> 2;
            int ch = tid & 3;
            const __half* g = B + (long long)(colBase + n) * KT + k0 + ch * 8;
            cp16(smem_u32(&Bs[buf][n * 40 + ch * 8]), g, 16);
        }
        cp_commit();
    };

    float acc[2][4][4] = {};
    loadTiles(0);

    // ldmatrix lane-address components (constant across iterations)
    const int aRow = (lane & 15);            // row within warp M-tile
    const int aKof = (lane >> 4) << 3;       // 0 or 8 (k-half)
    const int bRow = wn * 32 + lane;         // n row for B x4 (4 nt matrices)

#pragma unroll
    for (int i = 0; i < NK; i++) {
        if (i + 1 < NK) loadTiles(i + 1);
        if (i + 1 < NK) cp_wait<1>(); else cp_wait<0>();
        __syncthreads();

        const __half* as = As[i & 1];
        const __half* bs = Bs[i & 1];
#pragma unroll
        for (int ks = 0; ks < 32; ks += 16) {
            uint32_t a[2][4];
#pragma unroll
            for (int mt = 0; mt < 2; mt++) {
                uint32_t addr = smem_u32(as + (wm * 32 + mt * 16 + aRow) * 40 + ks + aKof);
                ldsm_x4(a[mt][0], a[mt][1], a[mt][2], a[mt][3], addr);
            }
            uint32_t b[2][4];   // [k-half][nt]
#pragma unroll
            for (int h = 0; h < 2; h++) {
                uint32_t addr = smem_u32(bs + bRow * 40 + ks + h * 8);
                ldsm_x4(b[h][0], b[h][1], b[h][2], b[h][3], addr);
            }
#pragma unroll
            for (int mt = 0; mt < 2; mt++)
#pragma unroll
                for (int nt = 0; nt < 4; nt++)
                    mma_f16(acc[mt][nt], a[mt][0], a[mt][1], a[mt][2], a[mt][3],
                            b[0][nt], b[1][nt]);
        }
        __syncthreads();
    }

    // epilogue: c0,c1 -> row gid (cols 2tig,2tig+1); c2,c3 -> row gid+8
#pragma unroll
    for (int mt = 0; mt < 2; mt++) {
#pragma unroll
        for (int h = 0; h < 2; h++) {
            int row = rowBase + wm * 32 + mt * 16 + gid + h * 8;
            if (row >= M) continue;
            float dv  = (MODE == 0) ? 0.f : dinv[row];
            float dv2 = dv * dv;
            long long rb = (long long)row * Ncol;
#pragma unroll
            for (int nt = 0; nt < 4; nt++) {
                int c = colBase + wn * 32 + nt * 8 + 2 * tig;
                float v0 = acc[mt][nt][2 * h + 0];
                float v1 = acc[mt][nt][2 * h + 1];
                if (MODE == 0) {
                    float2 bb = *(const float2*)(bias2 + c);
                    *(__half2*)(OutH + rb + c) =
                        __floats2half2_rn(fmaxf(v0 + bb.x, 0.f), fmaxf(v1 + bb.y, 0.f));
                } else if (MODE == 1) {
                    *(__half2*)(OutS + rb + c) = __floats2half2_rn(v0 * dv, v1 * dv);
                    float2 p2 = *(const float2*)(bias2 + c);
                    float2 p3 = *(const float2*)(bias3 + c);
                    *(float2*)(OutF + rb + c) =
                        make_float2(v0 * dv2 + p2.x + p3.x, v1 * dv2 + p2.y + p3.y);
                } else {
                    *(__half2*)(OutS + rb + c) = __floats2half2_rn(v0 * dv, v1 * dv);
                    float2 o = *(const float2*)(OutF + rb + c);
                    o.x += v0 * dv2;
                    o.y += v1 * dv2;
                    *(float2*)(OutF + rb + c) = o;
                }
            }
        }
    }
}

// ---------------------------------------------------------------------------
// host side: two-stream schedule = round-13/14 proven topology (H1 ∥ H2,
// MODE1 ∥ nothing, T1-gather ∥ H2+MODE2) + per-graph decode and 2-phase scan.
// All record-before-wait pairs in valid program order under capture.
// ---------------------------------------------------------------------------
static cudaStream_t g_s2    = nullptr;
static cudaEvent_t  g_evF   = nullptr;   // fork point (s0, first)
static cudaEvent_t  g_evW   = nullptr;   // weights prepped (s2)
static cudaEvent_t  g_evX1  = nullptr;   // after gather Xa1 (stagger gate, s0)
static cudaEvent_t  g_evH2  = nullptr;   // after GEMM H2 (s2)
static cudaEvent_t  g_evM1  = nullptr;   // after GEMM MODE1 (s0)
static cudaEvent_t  g_evT1  = nullptr;   // after gather T1 (s2, join point)

extern "C" void kernel_launch(void* const* d_in, const int* in_sizes, int n_in,
                              void* d_out, int out_size) {
    if (!g_s2) {
        cudaStreamCreateWithFlags(&g_s2, cudaStreamNonBlocking);
        cudaEventCreateWithFlags(&g_evF,  cudaEventDisableTiming);
        cudaEventCreateWithFlags(&g_evW,  cudaEventDisableTiming);
        cudaEventCreateWithFlags(&g_evX1, cudaEventDisableTiming);
        cudaEventCreateWithFlags(&g_evH2, cudaEventDisableTiming);
        cudaEventCreateWithFlags(&g_evM1, cudaEventDisableTiming);
        cudaEventCreateWithFlags(&g_evT1, cudaEventDisableTiming);
    }

    const float* x   = (const float*)d_in[0];
    const void*  ei  = d_in[1];
    const void*  ei2 = d_in[2];
    const float* W0 = (const float*)d_in[3];
    const float* b0 = (const float*)d_in[4];
    const float* W1 = (const float*)d_in[5];
    const float* b1 = (const float*)d_in[6];
    const float* W2 = (const float*)d_in[7];
    const float* b2 = (const float*)d_in[8];
    const float* W3 = (const float*)d_in[9];
    const float* b3 = (const float*)d_in[10];

    const int N = in_sizes[0] / 128;   // 50000
    const int E = in_sizes[1] / 2;     // 800000
    const int NB = (N + 1023) / 1024;  // scan blocks (49)

    float* S = nullptr;
    cudaGetSymbolAddress((void**)&S, g_scratch);
    float*  dinv1 = S + OFF_DINV1;
    float*  dinv2 = S + OFF_DINV2;
    int*    cnt1  = (int*)(S + OFF_CNT1);
    int*    cnt2  = (int*)(S + OFF_CNT2);
    int*    rp1   = (int*)(S + OFF_RP1);
    int*    rp2   = (int*)(S + OFF_RP2);
    int*    fp1   = (int*)(S + OFF_FP1);
    int*    fp2   = (int*)(S + OFF_FP2);
    int*    bs1   = (int*)(S + OFF_BS1);
    int*    bs2   = (int*)(S + OFF_BS2);
    int*    idx1  = (int*)(S + OFF_IDX1);
    int*    idx2  = (int*)(S + OFF_IDX2);
    int*    adj1  = (int*)(S + OFF_ADJ1);
    int*    adj2  = (int*)(S + OFF_ADJ2);
    __half* Xs1   = (__half*)(S + OFF_XS1);
    __half* Xs2   = (__half*)(S + OFF_XS2);
    __half* Xa1   = (__half*)(S + OFF_XA1);
    __half* Xa2   = (__half*)(S + OFF_XA2);
    __half* H1    = (__half*)(S + OFF_H1);
    __half* H2    = (__half*)(S + OFF_H2);
    __half* Gs1   = (__half*)(S + OFF_GS1);
    __half* Gs2   = (__half*)(S + OFF_GS2);
    float*  T1    = S + OFF_T1;
    __half* Wh0   = (__half*)(S + OFF_WH0);
    __half* Wh1   = (__half*)(S + OFF_WH1);
    __half* Wh2   = (__half*)(S + OFF_WH2);
    __half* Wh3   = (__half*)(S + OFF_WH3);
    float*  out   = (float*)d_out;

    cudaStream_t s0 = 0;
    cudaStream_t s2 = g_s2;

    const int* src1 = idx1;
    const int* dst1 = idx1 + E;
    const int* src2 = idx2;
    const int* dst2 = idx2 + E;

    // ---- (1) s0: dtype probe + zero BOTH counters, record evF
    {
        int words = (E < 65536) ? E : 65536;
        int span  = (2 * N > words) ? 2 * N : words;
        k_detect_zero<<<(span + 255) / 256, 256, 0, s0>>>((const long long*)ei, words, N, cnt1, 2 * N);
    }
    cudaEventRecord(g_evF, s0);

    // ---- (2) s2 joins capture: weight prep + graph-2 prelim chain
    cudaStreamWaitEvent(s2, g_evF, 0);
    k_prep_w<<<512, 256, 0, s2>>>(W0, W1, W2, W3, Wh0, Wh1, Wh2, Wh3);
    cudaEventRecord(g_evW, s2);
    k_convert_deg1<<<(2 * E + 255) / 256, 256, 0, s2>>>(ei2, idx2, 2 * E, E, cnt2);
    k_scan_a<<<NB, 1024, 0, s2>>>(cnt2, rp2, dinv2, bs2, N);
    k_scan_c<<<NB, 1024, 0, s2>>>(rp2, fp2, bs2, NB, N);
    k_fill1<<<(E + 255) / 256, 256, 0, s2>>>(src2, dst2, fp2, adj2, E);
    k_prescale_h<<<(N * 32 + 255) / 256, 256, 0, s2>>>((const float4*)x, dinv2, (uint2*)Xs2, N * 32);

    // ---- (3) s0: graph-1 chain, record evX1
    k_convert_deg1<<<(2 * E + 255) / 256, 256, 0, s0>>>(ei, idx1, 2 * E, E, cnt1);
    k_scan_a<<<NB, 1024, 0, s0>>>(cnt1, rp1, dinv1, bs1, N);
    k_scan_c<<<NB, 1024, 0, s0>>>(rp1, fp1, bs1, NB, N);
    k_fill1<<<(E + 255) / 256, 256, 0, s0>>>(src1, dst1, fp1, adj1, E);
    k_prescale_h<<<(N * 32 + 255) / 256, 256, 0, s0>>>((const float4*)x, dinv1, (uint2*)Xs1, N * 32);
    k_gather_xa<<<(N + 7) / 8, 256, 0, s0>>>(rp1, cnt1, adj1, dinv1, (const uint2*)Xs1,
                                             (const float4*)x, (uint2*)Xa1, N);
    cudaEventRecord(g_evX1, s0);

    // ---- (4) s2: gather Xa2 staggered after Xa1 (evX1 recorded above)
    cudaStreamWaitEvent(s2, g_evX1, 0);
    k_gather_xa<<<(N + 7) / 8, 256, 0, s2>>>(rp2, cnt2, adj2, dinv2, (const uint2*)Xs2,
                                             (const float4*)x, (uint2*)Xa2, N);

    // ---- (5) layer-1 GEMMs in PARALLEL: H1 on s0, H2 on s2
    dim3 g1(4, (N + 127) / 128);   // layer-1: KT=128, Ncol=256
    dim3 g2(2, (N + 127) / 128);   // layer-2: KT=256, Ncol=128
    cudaStreamWaitEvent(s0, g_evW, 0);
    k_gemm_h<0, 128><<<g1, 256, 0, s0>>>(Xa1, Wh0, nullptr, nullptr, H1, nullptr, b0, nullptr, N, 256);
    k_gemm_h<0, 128><<<g1, 256, 0, s2>>>(Xa2, Wh1, nullptr, nullptr, H2, nullptr, b1, nullptr, N, 256);
    cudaEventRecord(g_evH2, s2);

    // ---- (6) s0: MODE1 GEMM, record evM1
    k_gemm_h<1, 256><<<g2, 256, 0, s0>>>(H1, Wh2, dinv1, Gs1, nullptr, out, b2, b3, N, 128);
    cudaEventRecord(g_evM1, s0);

    // ---- (7) s2: graph-1 output gather into T1, hidden under H2+MODE2
    cudaStreamWaitEvent(s2, g_evM1, 0);
    k_gather_out<2><<<(N + 7) / 8, 256, 0, s2>>>(rp1, cnt1, adj1, dinv1, (const uint2*)Gs1,
                                                 nullptr, (float4*)T1, N);
    cudaEventRecord(g_evT1, s2);

    // ---- (8) s0: MODE2 GEMM after H2 completes
    cudaStreamWaitEvent(s0, g_evH2, 0);
    k_gemm_h<2, 256><<<g2, 256, 0, s0>>>(H2, Wh3, dinv2, Gs2, nullptr, out, nullptr, nullptr, N, 128);

    // ---- (9) s0: final graph-2 gather + T1 add fused into out (join on evT1)
    cudaStreamWaitEvent(s0, g_evT1, 0);
    k_gather_out<3><<<(N + 7) / 8, 256, 0, s0>>>(rp2, cnt2, adj2, dinv2, (const uint2*)Gs2,
                                                 (const float4*)T1, (float4*)out, N);
}